// round 13
// baseline (speedup 1.0000x reference)
#include <cuda_runtime.h>
#include <math.h>

#define BB 2
#define LL 2048
#define DM 1024
#define NH 16
#define DK 64
#define BH (BB*NH)

// ---------------- tf32 MMA helpers ----------------
__device__ __forceinline__ unsigned f2tf(float f) {
    unsigned u; asm("cvt.rna.tf32.f32 %0, %1;" : "=r"(u) : "f"(f)); return u;
}
__device__ __forceinline__ void mma8(float* c, const unsigned* a, const unsigned* b) {
    asm volatile("mma.sync.aligned.m16n8k8.row.col.f32.tf32.tf32.f32 "
        "{%0,%1,%2,%3}, {%4,%5,%6,%7}, {%8,%9}, {%0,%1,%2,%3};"
        : "+f"(c[0]), "+f"(c[1]), "+f"(c[2]), "+f"(c[3])
        : "r"(a[0]), "r"(a[1]), "r"(a[2]), "r"(a[3]), "r"(b[0]), "r"(b[1]));
}

// ---------------- scratch ----------------
__device__ float g_Q[(size_t)BB*NH*LL*DK];
__device__ float g_K[(size_t)BB*NH*LL*DK];
__device__ float g_V[(size_t)BB*NH*LL*DK];
__device__ float g_C[(size_t)BB*LL*DM];
__device__ float g_P[(size_t)BB*NH*LL*LL];
__device__ float g_m[(size_t)BB*NH*LL];
__device__ float g_s[(size_t)BB*NH*LL];
__device__ float g_c[(size_t)BB*NH*LL];
__device__ float g_rb[(size_t)BB*LL];
__device__ float g_WT[4][(size_t)DM*DM];   // transposed weights [n][k]

// ---------------- rel-bias precompute ----------------
__global__ void rb_kernel(const float* __restrict__ delta)
{
    int i = blockIdx.x * 256 + threadIdx.x;
    if (i < BB*LL) g_rb[i] = logf(delta[i] + 1e-6f);
}

// ---------------- weight transpose (once, 4 matrices) ----------------
__global__ void wt_kernel(const float* __restrict__ Wq, const float* __restrict__ Wk,
                          const float* __restrict__ Wv, const float* __restrict__ Wo)
{
    __shared__ float t[32][33];
    const int which = blockIdx.z;
    const float* W = (which == 0) ? Wq : (which == 1) ? Wk : (which == 2) ? Wv : Wo;
    const int x0 = blockIdx.x * 32, y0 = blockIdx.y * 32;
    const int tx = threadIdx.x, ty = threadIdx.y;
    #pragma unroll
    for (int i = 0; i < 32; i += 8)
        t[ty + i][tx] = W[(size_t)(y0 + ty + i) * DM + x0 + tx];
    __syncthreads();
    float* WT = g_WT[which];
    #pragma unroll
    for (int i = 0; i < 32; i += 8)
        WT[(size_t)(x0 + ty + i) * DM + y0 + tx] = t[tx][ty + i];
}

// =====================================================================
// QKV projection: tf32 MMA, 128m x 128n block, 8 warps of 16m x 128n.
// =====================================================================
__global__ __launch_bounds__(256) void qkv_tf32(
    const float* __restrict__ x, const float* __restrict__ delta,
    const float* __restrict__ bq, const float* __restrict__ bk,
    const float* __restrict__ bv)
{
    __shared__ unsigned Ws[128][76];   // [n][k] tf32

    const int which = blockIdx.z;
    const float* bias = (which == 0) ? bq : (which == 1) ? bk : bv;
    float* O          = (which == 0) ? g_Q : (which == 1) ? g_K : g_V;
    const float* WT   = g_WT[which];

    const int n0 = blockIdx.x * 128, m0 = blockIdx.y * 128;
    const int tid = threadIdx.x, lane = tid & 31, warp = tid >> 5;
    const int g = lane >> 2, t = lane & 3;

    const int row0 = m0 + warp * 16 + g, row1 = row0 + 8;
    float s0 = 1.0f, s1 = 1.0f;
    if (which == 2) { s0 = delta[row0]; s1 = delta[row1]; }

    const float* a0p = x + (size_t)row0 * DM + 2 * t;
    const float* a1p = x + (size_t)row1 * DM + 2 * t;

    const int wn = tid >> 1, wk0 = (tid & 1) * 32;
    const float* wfill = WT + (size_t)(n0 + wn) * DM + wk0;

    float c4[16][4] = {};

    for (int k0 = 0; k0 < DM; k0 += 64) {
        __syncthreads();
        #pragma unroll
        for (int c = 0; c < 8; c++) {
            float4 v = *(const float4*)(wfill + k0 + c * 4);
            unsigned u[4] = {f2tf(v.x), f2tf(v.y), f2tf(v.z), f2tf(v.w)};
            *(uint4*)&Ws[wn][wk0 + 4 * c] = *(uint4*)u;
        }
        __syncthreads();
        #pragma unroll
        for (int j = 0; j < 8; j++) {
            float2 lo = *(const float2*)(a0p + k0 + 8 * j);
            float2 hi = *(const float2*)(a1p + k0 + 8 * j);
            unsigned a[4] = {f2tf(lo.x * s0), f2tf(hi.x * s1),
                             f2tf(lo.y * s0), f2tf(hi.y * s1)};
            #pragma unroll
            for (int jn = 0; jn < 16; jn++) {
                uint2 bb = *(const uint2*)&Ws[jn * 8 + g][8 * j + 2 * t];
                unsigned bfr[2] = {bb.x, bb.y};
                mma8(c4[jn], a, bfr);
            }
        }
    }

    const int b0 = row0 >> 11, l0 = row0 & (LL - 1);
    const int b1 = row1 >> 11, l1 = row1 & (LL - 1);
    #pragma unroll
    for (int jn = 0; jn < 16; jn++) {
        int gn = n0 + jn * 8 + 2 * t;
        int h = gn >> 6, d = gn & 63;
        float bsx = bias[gn], bsy = bias[gn + 1];
        *(float2*)&O[(((size_t)(b0 * NH + h)) * LL + l0) * DK + d] =
            make_float2(c4[jn][0] + bsx, c4[jn][1] + bsy);
        *(float2*)&O[(((size_t)(b1 * NH + h)) * LL + l1) * DK + d] =
            make_float2(c4[jn][2] + bsx, c4[jn][3] + bsy);
    }
}

// =====================================================================
// Scores: Q frags in regs, K plain smem tile (pad 76)
// =====================================================================
__global__ __launch_bounds__(256, 2) void scores_kernel()
{
    __shared__ unsigned Ks[64][76];   // [key][d] tf32
    __shared__ float rbs[64];

    const int bh = blockIdx.y, b = bh >> 4;
    const int q0 = blockIdx.x * 128;
    const int tid = threadIdx.x, lane = tid & 31, warp = tid >> 5;
    const int g = lane >> 2, t = lane & 3;

    const int row0 = q0 + warp * 16 + g;
    const int row1 = row0 + 8;

    unsigned qa[8][4];
    {
        const float* q0p = &g_Q[((size_t)bh * LL + row0) * DK + 2 * t];
        const float* q1p = q0p + 8 * DK;
        #pragma unroll
        for (int j = 0; j < 8; j++) {
            float2 lo = *(const float2*)(q0p + 8 * j);
            float2 hi = *(const float2*)(q1p + 8 * j);
            qa[j][0] = f2tf(lo.x); qa[j][1] = f2tf(hi.x);
            qa[j][2] = f2tf(lo.y); qa[j][3] = f2tf(hi.y);
        }
    }

    float mr0 = -1e30f, sr0 = 0.0f, mr1 = -1e30f, sr1 = 0.0f;
    const float qr0 = (float)row0, qr1 = (float)row1;
    float* Prow0 = &g_P[((size_t)bh * LL + row0) * LL];
    float* Prow1 = &g_P[((size_t)bh * LL + row1) * LL];

    for (int kt = 0; kt < LL / 64; kt++) {
        __syncthreads();
        {
            int krow = tid >> 2, dseg = (tid & 3) * 16;
            const float* kp = &g_K[((size_t)bh * LL + kt * 64 + krow) * DK + dseg];
            #pragma unroll
            for (int c = 0; c < 4; c++) {
                float4 v = *(const float4*)(kp + c * 4);
                unsigned u[4] = {f2tf(v.x), f2tf(v.y), f2tf(v.z), f2tf(v.w)};
                *(uint4*)&Ks[krow][dseg + 4 * c] = *(uint4*)u;
            }
            if (tid < 64) rbs[tid] = g_rb[(size_t)b * LL + kt * 64 + tid];
        }
        __syncthreads();

        float c4[8][4] = {};
        #pragma unroll
        for (int j = 0; j < 8; j++) {
            #pragma unroll
            for (int jn = 0; jn < 8; jn++) {
                uint2 bb = *(const uint2*)&Ks[jn * 8 + g][8 * j + 2 * t];
                unsigned bfr[2] = {bb.x, bb.y};
                mma8(c4[jn], qa[j], bfr);
            }
        }

        float rbv[16];
        #pragma unroll
        for (int jn = 0; jn < 8; jn++) {
            rbv[2*jn]   = rbs[jn * 8 + 2 * t];
            rbv[2*jn+1] = rbs[jn * 8 + 2 * t + 1];
        }

        {
            float sv[16]; float vmax = -1e30f;
            #pragma unroll
            for (int jn = 0; jn < 8; jn++) {
                int kg = kt * 64 + jn * 8 + 2 * t;
                float v0 = c4[jn][0] * 0.125f - 0.1f * fabsf(qr0 - (float)kg)       + rbv[2*jn];
                float v1 = c4[jn][1] * 0.125f - 0.1f * fabsf(qr0 - (float)(kg + 1)) + rbv[2*jn+1];
                sv[2*jn] = v0; sv[2*jn+1] = v1;
                vmax = fmaxf(vmax, fmaxf(v0, v1));
                __stcs((float2*)&Prow0[kg], make_float2(v0, v1));
            }
            vmax = fmaxf(vmax, __shfl_xor_sync(0xffffffffu, vmax, 1));
            vmax = fmaxf(vmax, __shfl_xor_sync(0xffffffffu, vmax, 2));
            float newm = fmaxf(mr0, vmax);
            float se = 0.0f;
            #pragma unroll
            for (int u = 0; u < 16; u++) se += __expf(sv[u] - newm);
            se += __shfl_xor_sync(0xffffffffu, se, 1);
            se += __shfl_xor_sync(0xffffffffu, se, 2);
            sr0 = sr0 * __expf(mr0 - newm) + se;
            mr0 = newm;
        }
        {
            float sv[16]; float vmax = -1e30f;
            #pragma unroll
            for (int jn = 0; jn < 8; jn++) {
                int kg = kt * 64 + jn * 8 + 2 * t;
                float v0 = c4[jn][2] * 0.125f - 0.1f * fabsf(qr1 - (float)kg)       + rbv[2*jn];
                float v1 = c4[jn][3] * 0.125f - 0.1f * fabsf(qr1 - (float)(kg + 1)) + rbv[2*jn+1];
                sv[2*jn] = v0; sv[2*jn+1] = v1;
                vmax = fmaxf(vmax, fmaxf(v0, v1));
                __stcs((float2*)&Prow1[kg], make_float2(v0, v1));
            }
            vmax = fmaxf(vmax, __shfl_xor_sync(0xffffffffu, vmax, 1));
            vmax = fmaxf(vmax, __shfl_xor_sync(0xffffffffu, vmax, 2));
            float newm = fmaxf(mr1, vmax);
            float se = 0.0f;
            #pragma unroll
            for (int u = 0; u < 16; u++) se += __expf(sv[u] - newm);
            se += __shfl_xor_sync(0xffffffffu, se, 1);
            se += __shfl_xor_sync(0xffffffffu, se, 2);
            sr1 = sr1 * __expf(mr1 - newm) + se;
            mr1 = newm;
        }
    }

    if (t == 0) {
        size_t r0 = (size_t)bh * LL + row0;
        size_t r1 = (size_t)bh * LL + row1;
        g_m[r0] = mr0; g_s[r0] = sr0; g_c[r0] = mr0 + __logf(sr0);
        g_m[r1] = mr1; g_s[r1] = sr1; g_c[r1] = mr1 + __logf(sr1);
    }
}

// =====================================================================
// Context: P streamed gmem->reg, V plain smem tile (pad 76)
// =====================================================================
__global__ __launch_bounds__(256) void context_kernel()
{
    __shared__ unsigned Vs[64][76];   // [d][key] tf32

    const int bh = blockIdx.y, b = bh >> 4, hh = bh & 15;
    const int q0 = blockIdx.x * 128;
    const int tid = threadIdx.x, lane = tid & 31, warp = tid >> 5;
    const int g = lane >> 2, t = lane & 3;

    const int row0 = q0 + warp * 16 + g;
    const int row1 = row0 + 8;
    const float m0 = g_m[(size_t)bh * LL + row0];
    const float m1 = g_m[(size_t)bh * LL + row1];
    const float is0 = 1.0f / g_s[(size_t)bh * LL + row0];
    const float is1 = 1.0f / g_s[(size_t)bh * LL + row1];

    const float* Pr0 = &g_P[((size_t)bh * LL + row0) * LL + 2 * t];
    const float* Pr1 = Pr0 + 8 * LL;

    const int vd = tid & 63, vseg = tid >> 6;

    float c4[8][4] = {};

    for (int kc = 0; kc < LL; kc += 64) {
        __syncthreads();
        {
            const float* vb = &g_V[((size_t)bh * LL + kc + vseg * 16) * DK + vd];
            #pragma unroll
            for (int c = 0; c < 4; c++) {
                unsigned u[4];
                #pragma unroll
                for (int i2 = 0; i2 < 4; i2++)
                    u[i2] = f2tf(vb[(size_t)(c * 4 + i2) * DK]);
                *(uint4*)&Vs[vd][vseg * 16 + 4 * c] = *(uint4*)u;
            }
        }
        __syncthreads();

        #pragma unroll
        for (int j = 0; j < 8; j++) {
            float2 lo = __ldcs((const float2*)(Pr0 + kc + 8 * j));
            float2 hi = __ldcs((const float2*)(Pr1 + kc + 8 * j));
            unsigned a[4];
            a[0] = f2tf(__expf(lo.x - m0));
            a[1] = f2tf(__expf(hi.x - m1));
            a[2] = f2tf(__expf(lo.y - m0));
            a[3] = f2tf(__expf(hi.y - m1));
            #pragma unroll
            for (int jn = 0; jn < 8; jn++) {
                uint2 bb = *(const uint2*)&Vs[jn * 8 + g][8 * j + 2 * t];
                unsigned bfr[2] = {bb.x, bb.y};
                mma8(c4[jn], a, bfr);
            }
        }
    }

    float* Cr0 = &g_C[((size_t)(b * LL + row0)) * DM + hh * 64 + 2 * t];
    float* Cr1 = &g_C[((size_t)(b * LL + row1)) * DM + hh * 64 + 2 * t];
    #pragma unroll
    for (int jn = 0; jn < 8; jn++) {
        *(float2*)(Cr0 + jn * 8) = make_float2(c4[jn][0] * is0, c4[jn][1] * is0);
        *(float2*)(Cr1 + jn * 8) = make_float2(c4[jn][2] * is1, c4[jn][3] * is1);
    }
}

// =====================================================================
// Head-mean of attention
// =====================================================================
__global__ void mean_kernel(float* __restrict__ outmean)
{
    size_t idx4 = (size_t)blockIdx.x * 256 + threadIdx.x;
    int k4 = (int)(idx4 & (LL / 4 - 1)) * 4;
    size_t bq = idx4 / (LL / 4);
    int q = (int)(bq & (LL - 1));
    int b = (int)(bq >> 11);
    float ax = 0, ay = 0, az = 0, aw = 0;
    #pragma unroll
    for (int h = 0; h < NH; h++) {
        int bh = b * NH + h;
        float cc = g_c[(size_t)bh * LL + q];
        float4 v = __ldcs((const float4*)&g_P[((size_t)bh * LL + q) * LL + k4]);
        ax += __expf(v.x - cc); ay += __expf(v.y - cc);
        az += __expf(v.z - cc); aw += __expf(v.w - cc);
    }
    const float inv = 1.0f / NH;
    *(float4*)&outmean[bq * LL + k4] = make_float4(ax*inv, ay*inv, az*inv, aw*inv);
}

// =====================================================================
// Output projection: tf32 MMA, 128m x 128n block
// =====================================================================
__global__ __launch_bounds__(256) void out_tf32(const float* __restrict__ bo,
                                                float* __restrict__ out)
{
    __shared__ unsigned Ws[128][76];

    const float* WT = g_WT[3];
    const int n0 = blockIdx.x * 128, m0 = blockIdx.y * 128;
    const int tid = threadIdx.x, lane = tid & 31, warp = tid >> 5;
    const int g = lane >> 2, t = lane & 3;

    const int row0 = m0 + warp * 16 + g, row1 = row0 + 8;
    const float* a0p = g_C + (size_t)row0 * DM + 2 * t;
    const float* a1p = g_C + (size_t)row1 * DM + 2 * t;

    const int wn = tid >> 1, wk0 = (tid & 1) * 32;
    const float* wfill = WT + (size_t)(n0 + wn) * DM + wk0;

    float c4[16][4] = {};

    for (int k0 = 0; k0 < DM; k0 += 64) {
        __syncthreads();
        #pragma unroll
        for (int c = 0; c < 8; c++) {
            float4 v = *(const float4*)(wfill + k0 + c * 4);
            unsigned u[4] = {f2tf(v.x), f2tf(v.y), f2tf(v.z), f2tf(v.w)};
            *(uint4*)&Ws[wn][wk0 + 4 * c] = *(uint4*)u;
        }
        __syncthreads();
        #pragma unroll
        for (int j = 0; j < 8; j++) {
            float2 lo = *(const float2*)(a0p + k0 + 8 * j);
            float2 hi = *(const float2*)(a1p + k0 + 8 * j);
            unsigned a[4] = {f2tf(lo.x), f2tf(hi.x), f2tf(lo.y), f2tf(hi.y)};
            #pragma unroll
            for (int jn = 0; jn < 16; jn++) {
                uint2 bb = *(const uint2*)&Ws[jn * 8 + g][8 * j + 2 * t];
                unsigned bfr[2] = {bb.x, bb.y};
                mma8(c4[jn], a, bfr);
            }
        }
    }

    #pragma unroll
    for (int jn = 0; jn < 16; jn++) {
        int gn = n0 + jn * 8 + 2 * t;
        float bsx = bo[gn], bsy = bo[gn + 1];
        *(float2*)&out[(size_t)row0 * DM + gn] = make_float2(c4[jn][0] + bsx, c4[jn][1] + bsy);
        *(float2*)&out[(size_t)row1 * DM + gn] = make_float2(c4[jn][2] + bsx, c4[jn][3] + bsy);
    }
}

// ---------------- launch ----------------
extern "C" void kernel_launch(void* const* d_in, const int* in_sizes, int n_in,
                              void* d_out, int out_size)
{
    const float* x     = (const float*)d_in[0];
    const float* delta = (const float*)d_in[1];
    const float* Wq    = (const float*)d_in[2];
    const float* bq    = (const float*)d_in[3];
    const float* Wk    = (const float*)d_in[4];
    const float* bk    = (const float*)d_in[5];
    const float* Wv    = (const float*)d_in[6];
    const float* bv    = (const float*)d_in[7];
    const float* Wo    = (const float*)d_in[8];
    const float* bo    = (const float*)d_in[9];
    float* out = (float*)d_out;
    float* outmean = out + (size_t)BB * LL * DM;

    rb_kernel<<<(BB * LL + 255) / 256, 256>>>(delta);
    wt_kernel<<<dim3(32, 32, 4), dim3(32, 8)>>>(Wq, Wk, Wv, Wo);
    qkv_tf32<<<dim3(DM / 128, (BB * LL) / 128, 3), 256>>>(x, delta, bq, bk, bv);
    scores_kernel<<<dim3(LL / 128, BH), 256>>>();
    context_kernel<<<dim3(LL / 128, BH), 256>>>();
    mean_kernel<<<(unsigned)((size_t)BB * LL * LL / 4 / 256), 256>>>(outmean);
    out_tf32<<<dim3(DM / 128, (BB * LL) / 128), 256>>>(bo, out);
}

// round 15
// speedup vs baseline: 1.3117x; 1.3117x over previous
#include <cuda_runtime.h>
#include <math.h>

#define BB 2
#define LL 2048
#define DM 1024
#define NH 16
#define DK 64
#define BH (BB*NH)

// ---------------- tf32 MMA helpers ----------------
__device__ __forceinline__ unsigned f2tf(float f) {
    unsigned u; asm("cvt.rna.tf32.f32 %0, %1;" : "=r"(u) : "f"(f)); return u;
}
__device__ __forceinline__ void mma8(float* c, const unsigned* a, const unsigned* b) {
    asm volatile("mma.sync.aligned.m16n8k8.row.col.f32.tf32.tf32.f32 "
        "{%0,%1,%2,%3}, {%4,%5,%6,%7}, {%8,%9}, {%0,%1,%2,%3};"
        : "+f"(c[0]), "+f"(c[1]), "+f"(c[2]), "+f"(c[3])
        : "r"(a[0]), "r"(a[1]), "r"(a[2]), "r"(a[3]), "r"(b[0]), "r"(b[1]));
}

// ---------------- scratch ----------------
__device__ float g_Q[(size_t)BB*NH*LL*DK];
__device__ float g_K[(size_t)BB*NH*LL*DK];
__device__ float g_V[(size_t)BB*NH*LL*DK];
__device__ float g_C[(size_t)BB*LL*DM];
__device__ float g_P[(size_t)BB*NH*LL*LL];
__device__ float g_m[(size_t)BB*NH*LL];
__device__ float g_s[(size_t)BB*NH*LL];
__device__ float g_c[(size_t)BB*NH*LL];
__device__ float g_rb[(size_t)BB*LL];
__device__ float g_WT[4][(size_t)DM*DM];   // transposed weights [n][k]

// ---------------- rel-bias precompute ----------------
__global__ void rb_kernel(const float* __restrict__ delta)
{
    int i = blockIdx.x * 256 + threadIdx.x;
    if (i < BB*LL) g_rb[i] = logf(delta[i] + 1e-6f);
}

// ---------------- weight transpose (once, 4 matrices) ----------------
__global__ void wt_kernel(const float* __restrict__ Wq, const float* __restrict__ Wk,
                          const float* __restrict__ Wv, const float* __restrict__ Wo)
{
    __shared__ float t[32][33];
    const int which = blockIdx.z;
    const float* W = (which == 0) ? Wq : (which == 1) ? Wk : (which == 2) ? Wv : Wo;
    const int x0 = blockIdx.x * 32, y0 = blockIdx.y * 32;
    const int tx = threadIdx.x, ty = threadIdx.y;
    #pragma unroll
    for (int i = 0; i < 32; i += 8)
        t[ty + i][tx] = W[(size_t)(y0 + ty + i) * DM + x0 + tx];
    __syncthreads();
    float* WT = g_WT[which];
    #pragma unroll
    for (int i = 0; i < 32; i += 8)
        WT[(size_t)(x0 + ty + i) * DM + y0 + tx] = t[tx][ty + i];
}

// =====================================================================
// QKV projection: tf32 MMA, 128m x 64n block  [proven R12]
// =====================================================================
__global__ __launch_bounds__(256) void qkv_tf32(
    const float* __restrict__ x, const float* __restrict__ delta,
    const float* __restrict__ bq, const float* __restrict__ bk,
    const float* __restrict__ bv)
{
    __shared__ unsigned Ws[64][72];   // [n][k] tf32

    const int which = blockIdx.z;
    const float* bias = (which == 0) ? bq : (which == 1) ? bk : bv;
    float* O          = (which == 0) ? g_Q : (which == 1) ? g_K : g_V;
    const float* WT   = g_WT[which];

    const int n0 = blockIdx.x * 64, m0 = blockIdx.y * 128;
    const int tid = threadIdx.x, lane = tid & 31, warp = tid >> 5;
    const int g = lane >> 2, t = lane & 3;

    const int row0 = m0 + warp * 16 + g, row1 = row0 + 8;
    float s0 = 1.0f, s1 = 1.0f;
    if (which == 2) { s0 = delta[row0]; s1 = delta[row1]; }

    const float* a0p = x + (size_t)row0 * DM + 2 * t;
    const float* a1p = x + (size_t)row1 * DM + 2 * t;

    const int wn = tid >> 2, wk = (tid & 3) * 16;
    const float* wfill = WT + (size_t)(n0 + wn) * DM + wk;

    float c4[8][4] = {};

    for (int k0 = 0; k0 < DM; k0 += 64) {
        __syncthreads();
        #pragma unroll
        for (int c = 0; c < 4; c++) {
            float4 v = *(const float4*)(wfill + k0 + c * 4);
            unsigned u[4] = {f2tf(v.x), f2tf(v.y), f2tf(v.z), f2tf(v.w)};
            *(uint4*)&Ws[wn][wk + 4 * c] = *(uint4*)u;
        }
        __syncthreads();
        #pragma unroll
        for (int j = 0; j < 8; j++) {
            float2 lo = *(const float2*)(a0p + k0 + 8 * j);
            float2 hi = *(const float2*)(a1p + k0 + 8 * j);
            unsigned a[4] = {f2tf(lo.x * s0), f2tf(hi.x * s1),
                             f2tf(lo.y * s0), f2tf(hi.y * s1)};
            #pragma unroll
            for (int jn = 0; jn < 8; jn++) {
                uint2 bb = *(const uint2*)&Ws[jn * 8 + g][8 * j + 2 * t];
                unsigned bfr[2] = {bb.x, bb.y};
                mma8(c4[jn], a, bfr);
            }
        }
    }

    const int b0 = row0 >> 11, l0 = row0 & (LL - 1);
    const int b1 = row1 >> 11, l1 = row1 & (LL - 1);
    #pragma unroll
    for (int jn = 0; jn < 8; jn++) {
        int gn = n0 + jn * 8 + 2 * t;
        int h = gn >> 6, d = gn & 63;
        float bsx = bias[gn], bsy = bias[gn + 1];
        *(float2*)&O[(((size_t)(b0 * NH + h)) * LL + l0) * DK + d] =
            make_float2(c4[jn][0] + bsx, c4[jn][1] + bsy);
        *(float2*)&O[(((size_t)(b1 * NH + h)) * LL + l1) * DK + d] =
            make_float2(c4[jn][2] + bsx, c4[jn][3] + bsy);
    }
}

// =====================================================================
// Scores: Q frags in regs, K plain smem tile (pad 72).
// NEW: diagonal-first tile order + sub-threshold epilogue skip.
// =====================================================================
__global__ __launch_bounds__(256, 2) void scores_kernel()
{
    __shared__ unsigned Ks[64][72];   // [key][d] tf32
    __shared__ float rbs[64];

    const int bh = blockIdx.y, b = bh >> 4;
    const int q0 = blockIdx.x * 128;
    const int tid = threadIdx.x, lane = tid & 31, warp = tid >> 5;
    const int g = lane >> 2, t = lane & 3;
    const unsigned qmask = 0xFu << ((lane >> 2) << 2);   // 4-lane stat group

    const int row0 = q0 + warp * 16 + g;
    const int row1 = row0 + 8;

    unsigned qa[8][4];
    {
        const float* q0p = &g_Q[((size_t)bh * LL + row0) * DK + 2 * t];
        const float* q1p = q0p + 8 * DK;
        #pragma unroll
        for (int j = 0; j < 8; j++) {
            float2 lo = *(const float2*)(q0p + 8 * j);
            float2 hi = *(const float2*)(q1p + 8 * j);
            qa[j][0] = f2tf(lo.x); qa[j][1] = f2tf(hi.x);
            qa[j][2] = f2tf(lo.y); qa[j][3] = f2tf(hi.y);
        }
    }

    float mr0 = -1e30f, sr0 = 0.0f, mr1 = -1e30f, sr1 = 0.0f;
    const float qr0 = (float)row0, qr1 = (float)row1;
    float* Prow0 = &g_P[((size_t)bh * LL + row0) * LL];
    float* Prow1 = &g_P[((size_t)bh * LL + row1) * LL];

    // diagonal-first tile ordering: establish max early so far tiles skip
    int hi_t = q0 >> 6, lo_t = (q0 >> 6) - 1;

    for (int s = 0; s < LL / 64; s++) {
        int kt;
        if ((s & 1) == 0) { if (hi_t < LL / 64) kt = hi_t++; else kt = lo_t--; }
        else              { if (lo_t >= 0)      kt = lo_t--; else kt = hi_t++; }

        __syncthreads();
        {
            int krow = tid >> 2, dseg = (tid & 3) * 16;
            const float* kp = &g_K[((size_t)bh * LL + kt * 64 + krow) * DK + dseg];
            #pragma unroll
            for (int c = 0; c < 4; c++) {
                float4 v = *(const float4*)(kp + c * 4);
                unsigned u[4] = {f2tf(v.x), f2tf(v.y), f2tf(v.z), f2tf(v.w)};
                *(uint4*)&Ks[krow][dseg + 4 * c] = *(uint4*)u;
            }
            if (tid < 64) rbs[tid] = g_rb[(size_t)b * LL + kt * 64 + tid];
        }
        __syncthreads();

        float c4[8][4] = {};
        #pragma unroll
        for (int j = 0; j < 8; j++) {
            #pragma unroll
            for (int jn = 0; jn < 8; jn++) {
                uint2 bb = *(const uint2*)&Ks[jn * 8 + g][8 * j + 2 * t];
                unsigned bfr[2] = {bb.x, bb.y};
                mma8(c4[jn], qa[j], bfr);
            }
        }

        float rbv[16];
        #pragma unroll
        for (int jn = 0; jn < 8; jn++) {
            rbv[2*jn]   = rbs[jn * 8 + 2 * t];
            rbv[2*jn+1] = rbs[jn * 8 + 2 * t + 1];
        }

        // ---- row 0 ----
        {
            float sv[16]; float vmax = -1e30f;
            #pragma unroll
            for (int jn = 0; jn < 8; jn++) {
                int kg = kt * 64 + jn * 8 + 2 * t;
                float v0 = c4[jn][0] * 0.125f - 0.1f * fabsf(qr0 - (float)kg)       + rbv[2*jn];
                float v1 = c4[jn][1] * 0.125f - 0.1f * fabsf(qr0 - (float)(kg + 1)) + rbv[2*jn+1];
                sv[2*jn] = v0; sv[2*jn+1] = v1;
                vmax = fmaxf(vmax, fmaxf(v0, v1));
                __stcs((float2*)&Prow0[kg], make_float2(v0, v1));
            }
            vmax = fmaxf(vmax, __shfl_xor_sync(qmask, vmax, 1));
            vmax = fmaxf(vmax, __shfl_xor_sync(qmask, vmax, 2));
            if (vmax > mr0 - 25.0f) {   // else: contribution < e^-25, fp32 no-op
                float newm = fmaxf(mr0, vmax);
                float se = 0.0f;
                #pragma unroll
                for (int u = 0; u < 16; u++) se += __expf(sv[u] - newm);
                se += __shfl_xor_sync(qmask, se, 1);
                se += __shfl_xor_sync(qmask, se, 2);
                sr0 = sr0 * __expf(mr0 - newm) + se;
                mr0 = newm;
            }
        }
        // ---- row 1 ----
        {
            float sv[16]; float vmax = -1e30f;
            #pragma unroll
            for (int jn = 0; jn < 8; jn++) {
                int kg = kt * 64 + jn * 8 + 2 * t;
                float v0 = c4[jn][2] * 0.125f - 0.1f * fabsf(qr1 - (float)kg)       + rbv[2*jn];
                float v1 = c4[jn][3] * 0.125f - 0.1f * fabsf(qr1 - (float)(kg + 1)) + rbv[2*jn+1];
                sv[2*jn] = v0; sv[2*jn+1] = v1;
                vmax = fmaxf(vmax, fmaxf(v0, v1));
                __stcs((float2*)&Prow1[kg], make_float2(v0, v1));
            }
            vmax = fmaxf(vmax, __shfl_xor_sync(qmask, vmax, 1));
            vmax = fmaxf(vmax, __shfl_xor_sync(qmask, vmax, 2));
            if (vmax > mr1 - 25.0f) {
                float newm = fmaxf(mr1, vmax);
                float se = 0.0f;
                #pragma unroll
                for (int u = 0; u < 16; u++) se += __expf(sv[u] - newm);
                se += __shfl_xor_sync(qmask, se, 1);
                se += __shfl_xor_sync(qmask, se, 2);
                sr1 = sr1 * __expf(mr1 - newm) + se;
                mr1 = newm;
            }
        }
    }

    if (t == 0) {
        size_t r0 = (size_t)bh * LL + row0;
        size_t r1 = (size_t)bh * LL + row1;
        g_m[r0] = mr0; g_s[r0] = sr0; g_c[r0] = mr0 + __logf(sr0);
        g_m[r1] = mr1; g_s[r1] = sr1; g_c[r1] = mr1 + __logf(sr1);
    }
}

// =====================================================================
// Context: P streamed gmem->reg, V plain smem tile (pad 72)  [proven R12]
// =====================================================================
__global__ __launch_bounds__(256) void context_kernel()
{
    __shared__ unsigned Vs[64][72];   // [d][key] tf32

    const int bh = blockIdx.y, b = bh >> 4, hh = bh & 15;
    const int q0 = blockIdx.x * 128;
    const int tid = threadIdx.x, lane = tid & 31, warp = tid >> 5;
    const int g = lane >> 2, t = lane & 3;

    const int row0 = q0 + warp * 16 + g;
    const int row1 = row0 + 8;
    const float m0 = g_m[(size_t)bh * LL + row0];
    const float m1 = g_m[(size_t)bh * LL + row1];
    const float is0 = 1.0f / g_s[(size_t)bh * LL + row0];
    const float is1 = 1.0f / g_s[(size_t)bh * LL + row1];

    const float* Pr0 = &g_P[((size_t)bh * LL + row0) * LL + 2 * t];
    const float* Pr1 = Pr0 + 8 * LL;

    const int vd = tid & 63, vseg = tid >> 6;

    float c4[8][4] = {};

    for (int kc = 0; kc < LL; kc += 64) {
        __syncthreads();
        {
            const float* vb = &g_V[((size_t)bh * LL + kc + vseg * 16) * DK + vd];
            #pragma unroll
            for (int c = 0; c < 4; c++) {
                unsigned u[4];
                #pragma unroll
                for (int i2 = 0; i2 < 4; i2++)
                    u[i2] = f2tf(vb[(size_t)(c * 4 + i2) * DK]);
                *(uint4*)&Vs[vd][vseg * 16 + 4 * c] = *(uint4*)u;
            }
        }
        __syncthreads();

        #pragma unroll
        for (int j = 0; j < 8; j++) {
            float2 lo = __ldcs((const float2*)(Pr0 + kc + 8 * j));
            float2 hi = __ldcs((const float2*)(Pr1 + kc + 8 * j));
            unsigned a[4];
            a[0] = f2tf(__expf(lo.x - m0));
            a[1] = f2tf(__expf(hi.x - m1));
            a[2] = f2tf(__expf(lo.y - m0));
            a[3] = f2tf(__expf(hi.y - m1));
            #pragma unroll
            for (int jn = 0; jn < 8; jn++) {
                uint2 bb = *(const uint2*)&Vs[jn * 8 + g][8 * j + 2 * t];
                unsigned bfr[2] = {bb.x, bb.y};
                mma8(c4[jn], a, bfr);
            }
        }
    }

    float* Cr0 = &g_C[((size_t)(b * LL + row0)) * DM + hh * 64 + 2 * t];
    float* Cr1 = &g_C[((size_t)(b * LL + row1)) * DM + hh * 64 + 2 * t];
    #pragma unroll
    for (int jn = 0; jn < 8; jn++) {
        *(float2*)(Cr0 + jn * 8) = make_float2(c4[jn][0] * is0, c4[jn][1] * is0);
        *(float2*)(Cr1 + jn * 8) = make_float2(c4[jn][2] * is1, c4[jn][3] * is1);
    }
}

// =====================================================================
// Head-mean of attention
// =====================================================================
__global__ void mean_kernel(float* __restrict__ outmean)
{
    size_t idx4 = (size_t)blockIdx.x * 256 + threadIdx.x;
    int k4 = (int)(idx4 & (LL / 4 - 1)) * 4;
    size_t bq = idx4 / (LL / 4);
    int q = (int)(bq & (LL - 1));
    int b = (int)(bq >> 11);
    float ax = 0, ay = 0, az = 0, aw = 0;
    #pragma unroll
    for (int h = 0; h < NH; h++) {
        int bh = b * NH + h;
        float cc = g_c[(size_t)bh * LL + q];
        float4 v = __ldcs((const float4*)&g_P[((size_t)bh * LL + q) * LL + k4]);
        ax += __expf(v.x - cc); ay += __expf(v.y - cc);
        az += __expf(v.z - cc); aw += __expf(v.w - cc);
    }
    const float inv = 1.0f / NH;
    *(float4*)&outmean[bq * LL + k4] = make_float4(ax*inv, ay*inv, az*inv, aw*inv);
}

// =====================================================================
// Output projection: tf32 MMA, 128m x 64n block  [proven R12]
// =====================================================================
__global__ __launch_bounds__(256) void out_tf32(const float* __restrict__ bo,
                                                float* __restrict__ out)
{
    __shared__ unsigned Ws[64][72];

    const float* WT = g_WT[3];
    const int n0 = blockIdx.x * 64, m0 = blockIdx.y * 128;
    const int tid = threadIdx.x, lane = tid & 31, warp = tid >> 5;
    const int g = lane >> 2, t = lane & 3;

    const int row0 = m0 + warp * 16 + g, row1 = row0 + 8;
    const float* a0p = g_C + (size_t)row0 * DM + 2 * t;
    const float* a1p = g_C + (size_t)row1 * DM + 2 * t;

    const int wn = tid >> 2, wk = (tid & 3) * 16;
    const float* wfill = WT + (size_t)(n0 + wn) * DM + wk;

    float c4[8][4] = {};

    for (int k0 = 0; k0 < DM; k0 += 64) {
        __syncthreads();
        #pragma unroll
        for (int c = 0; c < 4; c++) {
            float4 v = *(const float4*)(wfill + k0 + c * 4);
            unsigned u[4] = {f2tf(v.x), f2tf(v.y), f2tf(v.z), f2tf(v.w)};
            *(uint4*)&Ws[wn][wk + 4 * c] = *(uint4*)u;
        }
        __syncthreads();
        #pragma unroll
        for (int j = 0; j < 8; j++) {
            float2 lo = *(const float2*)(a0p + k0 + 8 * j);
            float2 hi = *(const float2*)(a1p + k0 + 8 * j);
            unsigned a[4] = {f2tf(lo.x), f2tf(hi.x), f2tf(lo.y), f2tf(hi.y)};
            #pragma unroll
            for (int jn = 0; jn < 8; jn++) {
                uint2 bb = *(const uint2*)&Ws[jn * 8 + g][8 * j + 2 * t];
                unsigned bfr[2] = {bb.x, bb.y};
                mma8(c4[jn], a, bfr);
            }
        }
    }

    #pragma unroll
    for (int jn = 0; jn < 8; jn++) {
        int gn = n0 + jn * 8 + 2 * t;
        float bsx = bo[gn], bsy = bo[gn + 1];
        *(float2*)&out[(size_t)row0 * DM + gn] = make_float2(c4[jn][0] + bsx, c4[jn][1] + bsy);
        *(float2*)&out[(size_t)row1 * DM + gn] = make_float2(c4[jn][2] + bsx, c4[jn][3] + bsy);
    }
}

// ---------------- launch ----------------
extern "C" void kernel_launch(void* const* d_in, const int* in_sizes, int n_in,
                              void* d_out, int out_size)
{
    const float* x     = (const float*)d_in[0];
    const float* delta = (const float*)d_in[1];
    const float* Wq    = (const float*)d_in[2];
    const float* bq    = (const float*)d_in[3];
    const float* Wk    = (const float*)d_in[4];
    const float* bk    = (const float*)d_in[5];
    const float* Wv    = (const float*)d_in[6];
    const float* bv    = (const float*)d_in[7];
    const float* Wo    = (const float*)d_in[8];
    const float* bo    = (const float*)d_in[9];
    float* out = (float*)d_out;
    float* outmean = out + (size_t)BB * LL * DM;

    rb_kernel<<<(BB * LL + 255) / 256, 256>>>(delta);
    wt_kernel<<<dim3(32, 32, 4), dim3(32, 8)>>>(Wq, Wk, Wv, Wo);
    qkv_tf32<<<dim3(DM / 64, (BB * LL) / 128, 3), 256>>>(x, delta, bq, bk, bv);
    scores_kernel<<<dim3(LL / 128, BH), 256>>>();
    context_kernel<<<dim3(LL / 128, BH), 256>>>();
    mean_kernel<<<(unsigned)((size_t)BB * LL * LL / 4 / 256), 256>>>(outmean);
    out_tf32<<<dim3(DM / 64, (BB * LL) / 128), 256>>>(bo, out);
}

// round 16
// speedup vs baseline: 1.4173x; 1.0804x over previous
#include <cuda_runtime.h>
#include <math.h>
#include <stdlib.h>

#define BB 2
#define LL 2048
#define DM 1024
#define NH 16
#define DK 64
#define BH (BB*NH)
#define SKIPT 16   // tile-distance cutoff: |qtile-ktile| >= 16 -> prob < e^-74

// ---------------- tf32 MMA helpers ----------------
__device__ __forceinline__ unsigned f2tf(float f) {
    unsigned u; asm("cvt.rna.tf32.f32 %0, %1;" : "=r"(u) : "f"(f)); return u;
}
__device__ __forceinline__ void mma8(float* c, const unsigned* a, const unsigned* b) {
    asm volatile("mma.sync.aligned.m16n8k8.row.col.f32.tf32.tf32.f32 "
        "{%0,%1,%2,%3}, {%4,%5,%6,%7}, {%8,%9}, {%0,%1,%2,%3};"
        : "+f"(c[0]), "+f"(c[1]), "+f"(c[2]), "+f"(c[3])
        : "r"(a[0]), "r"(a[1]), "r"(a[2]), "r"(a[3]), "r"(b[0]), "r"(b[1]));
}

// ---------------- scratch ----------------
__device__ float g_Q[(size_t)BB*NH*LL*DK];
__device__ float g_K[(size_t)BB*NH*LL*DK];
__device__ float g_V[(size_t)BB*NH*LL*DK];
__device__ float g_C[(size_t)BB*LL*DM];
__device__ float g_P[(size_t)BB*NH*LL*LL];
__device__ float g_m[(size_t)BB*NH*LL];
__device__ float g_s[(size_t)BB*NH*LL];
__device__ float g_c[(size_t)BB*NH*LL];
__device__ float g_rb[(size_t)BB*LL];
__device__ float g_WT[4][(size_t)DM*DM];   // transposed weights [n][k]

// ---------------- rel-bias precompute ----------------
__global__ void rb_kernel(const float* __restrict__ delta)
{
    int i = blockIdx.x * 256 + threadIdx.x;
    if (i < BB*LL) g_rb[i] = logf(delta[i] + 1e-6f);
}

// ---------------- weight transpose (once, 4 matrices) ----------------
__global__ void wt_kernel(const float* __restrict__ Wq, const float* __restrict__ Wk,
                          const float* __restrict__ Wv, const float* __restrict__ Wo)
{
    __shared__ float t[32][33];
    const int which = blockIdx.z;
    const float* W = (which == 0) ? Wq : (which == 1) ? Wk : (which == 2) ? Wv : Wo;
    const int x0 = blockIdx.x * 32, y0 = blockIdx.y * 32;
    const int tx = threadIdx.x, ty = threadIdx.y;
    #pragma unroll
    for (int i = 0; i < 32; i += 8)
        t[ty + i][tx] = W[(size_t)(y0 + ty + i) * DM + x0 + tx];
    __syncthreads();
    float* WT = g_WT[which];
    #pragma unroll
    for (int i = 0; i < 32; i += 8)
        WT[(size_t)(x0 + ty + i) * DM + y0 + tx] = t[tx][ty + i];
}

// =====================================================================
// QKV projection: tf32 MMA, 128m x 64n block  [proven R12]
// =====================================================================
__global__ __launch_bounds__(256) void qkv_tf32(
    const float* __restrict__ x, const float* __restrict__ delta,
    const float* __restrict__ bq, const float* __restrict__ bk,
    const float* __restrict__ bv)
{
    __shared__ unsigned Ws[64][72];   // [n][k] tf32

    const int which = blockIdx.z;
    const float* bias = (which == 0) ? bq : (which == 1) ? bk : bv;
    float* O          = (which == 0) ? g_Q : (which == 1) ? g_K : g_V;
    const float* WT   = g_WT[which];

    const int n0 = blockIdx.x * 64, m0 = blockIdx.y * 128;
    const int tid = threadIdx.x, lane = tid & 31, warp = tid >> 5;
    const int g = lane >> 2, t = lane & 3;

    const int row0 = m0 + warp * 16 + g, row1 = row0 + 8;
    float s0 = 1.0f, s1 = 1.0f;
    if (which == 2) { s0 = delta[row0]; s1 = delta[row1]; }

    const float* a0p = x + (size_t)row0 * DM + 2 * t;
    const float* a1p = x + (size_t)row1 * DM + 2 * t;

    const int wn = tid >> 2, wk = (tid & 3) * 16;
    const float* wfill = WT + (size_t)(n0 + wn) * DM + wk;

    float c4[8][4] = {};

    for (int k0 = 0; k0 < DM; k0 += 64) {
        __syncthreads();
        #pragma unroll
        for (int c = 0; c < 4; c++) {
            float4 v = *(const float4*)(wfill + k0 + c * 4);
            unsigned u[4] = {f2tf(v.x), f2tf(v.y), f2tf(v.z), f2tf(v.w)};
            *(uint4*)&Ws[wn][wk + 4 * c] = *(uint4*)u;
        }
        __syncthreads();
        #pragma unroll
        for (int j = 0; j < 8; j++) {
            float2 lo = *(const float2*)(a0p + k0 + 8 * j);
            float2 hi = *(const float2*)(a1p + k0 + 8 * j);
            unsigned a[4] = {f2tf(lo.x * s0), f2tf(hi.x * s1),
                             f2tf(lo.y * s0), f2tf(hi.y * s1)};
            #pragma unroll
            for (int jn = 0; jn < 8; jn++) {
                uint2 bb = *(const uint2*)&Ws[jn * 8 + g][8 * j + 2 * t];
                unsigned bfr[2] = {bb.x, bb.y};
                mma8(c4[jn], a, bfr);
            }
        }
    }

    const int b0 = row0 >> 11, l0 = row0 & (LL - 1);
    const int b1 = row1 >> 11, l1 = row1 & (LL - 1);
    #pragma unroll
    for (int jn = 0; jn < 8; jn++) {
        int gn = n0 + jn * 8 + 2 * t;
        int h = gn >> 6, d = gn & 63;
        float bsx = bias[gn], bsy = bias[gn + 1];
        *(float2*)&O[(((size_t)(b0 * NH + h)) * LL + l0) * DK + d] =
            make_float2(c4[jn][0] + bsx, c4[jn][1] + bsy);
        *(float2*)&O[(((size_t)(b1 * NH + h)) * LL + l1) * DK + d] =
            make_float2(c4[jn][2] + bsx, c4[jn][3] + bsy);
    }
}

// =====================================================================
// Scores: Q frags in regs, K plain smem tile (pad 72).
// Diagonal-first order + epilogue skip + NEW provable tile cutoff.
// =====================================================================
__global__ __launch_bounds__(256, 2) void scores_kernel()
{
    __shared__ unsigned Ks[64][72];   // [key][d] tf32
    __shared__ float rbs[64];

    const int bh = blockIdx.y, b = bh >> 4;
    const int q0 = blockIdx.x * 128;
    const int tid = threadIdx.x, lane = tid & 31, warp = tid >> 5;
    const int g = lane >> 2, t = lane & 3;
    const unsigned qmask = 0xFu << ((lane >> 2) << 2);   // 4-lane stat group

    const int row0 = q0 + warp * 16 + g;
    const int row1 = row0 + 8;
    const int qt = row0 >> 6;   // row1 is in the same 64-tile

    unsigned qa[8][4];
    {
        const float* q0p = &g_Q[((size_t)bh * LL + row0) * DK + 2 * t];
        const float* q1p = q0p + 8 * DK;
        #pragma unroll
        for (int j = 0; j < 8; j++) {
            float2 lo = *(const float2*)(q0p + 8 * j);
            float2 hi = *(const float2*)(q1p + 8 * j);
            qa[j][0] = f2tf(lo.x); qa[j][1] = f2tf(hi.x);
            qa[j][2] = f2tf(lo.y); qa[j][3] = f2tf(hi.y);
        }
    }

    float mr0 = -1e30f, sr0 = 0.0f, mr1 = -1e30f, sr1 = 0.0f;
    const float qr0 = (float)row0, qr1 = (float)row1;
    float* Prow0 = &g_P[((size_t)bh * LL + row0) * LL];
    float* Prow1 = &g_P[((size_t)bh * LL + row1) * LL];

    // diagonal-first tile ordering
    int hi_t = q0 >> 6, lo_t = (q0 >> 6) - 1;

    for (int s = 0; s < LL / 64; s++) {
        int kt;
        if ((s & 1) == 0) { if (hi_t < LL / 64) kt = hi_t++; else kt = lo_t--; }
        else              { if (lo_t >= 0)      kt = lo_t--; else kt = hi_t++; }

        __syncthreads();
        {
            int krow = tid >> 2, dseg = (tid & 3) * 16;
            const float* kp = &g_K[((size_t)bh * LL + kt * 64 + krow) * DK + dseg];
            #pragma unroll
            for (int c = 0; c < 4; c++) {
                float4 v = *(const float4*)(kp + c * 4);
                unsigned u[4] = {f2tf(v.x), f2tf(v.y), f2tf(v.z), f2tf(v.w)};
                *(uint4*)&Ks[krow][dseg + 4 * c] = *(uint4*)u;
            }
            if (tid < 64) rbs[tid] = g_rb[(size_t)b * LL + kt * 64 + tid];
        }
        __syncthreads();

        if (abs(qt - kt) >= SKIPT) continue;   // prob < e^-74: tile is dead

        float c4[8][4] = {};
        #pragma unroll
        for (int j = 0; j < 8; j++) {
            #pragma unroll
            for (int jn = 0; jn < 8; jn++) {
                uint2 bb = *(const uint2*)&Ks[jn * 8 + g][8 * j + 2 * t];
                unsigned bfr[2] = {bb.x, bb.y};
                mma8(c4[jn], qa[j], bfr);
            }
        }

        float rbv[16];
        #pragma unroll
        for (int jn = 0; jn < 8; jn++) {
            rbv[2*jn]   = rbs[jn * 8 + 2 * t];
            rbv[2*jn+1] = rbs[jn * 8 + 2 * t + 1];
        }

        // ---- row 0 ----
        {
            float sv[16]; float vmax = -1e30f;
            #pragma unroll
            for (int jn = 0; jn < 8; jn++) {
                int kg = kt * 64 + jn * 8 + 2 * t;
                float v0 = c4[jn][0] * 0.125f - 0.1f * fabsf(qr0 - (float)kg)       + rbv[2*jn];
                float v1 = c4[jn][1] * 0.125f - 0.1f * fabsf(qr0 - (float)(kg + 1)) + rbv[2*jn+1];
                sv[2*jn] = v0; sv[2*jn+1] = v1;
                vmax = fmaxf(vmax, fmaxf(v0, v1));
                __stcs((float2*)&Prow0[kg], make_float2(v0, v1));
            }
            vmax = fmaxf(vmax, __shfl_xor_sync(qmask, vmax, 1));
            vmax = fmaxf(vmax, __shfl_xor_sync(qmask, vmax, 2));
            if (vmax > mr0 - 25.0f) {
                float newm = fmaxf(mr0, vmax);
                float se = 0.0f;
                #pragma unroll
                for (int u = 0; u < 16; u++) se += __expf(sv[u] - newm);
                se += __shfl_xor_sync(qmask, se, 1);
                se += __shfl_xor_sync(qmask, se, 2);
                sr0 = sr0 * __expf(mr0 - newm) + se;
                mr0 = newm;
            }
        }
        // ---- row 1 ----
        {
            float sv[16]; float vmax = -1e30f;
            #pragma unroll
            for (int jn = 0; jn < 8; jn++) {
                int kg = kt * 64 + jn * 8 + 2 * t;
                float v0 = c4[jn][2] * 0.125f - 0.1f * fabsf(qr1 - (float)kg)       + rbv[2*jn];
                float v1 = c4[jn][3] * 0.125f - 0.1f * fabsf(qr1 - (float)(kg + 1)) + rbv[2*jn+1];
                sv[2*jn] = v0; sv[2*jn+1] = v1;
                vmax = fmaxf(vmax, fmaxf(v0, v1));
                __stcs((float2*)&Prow1[kg], make_float2(v0, v1));
            }
            vmax = fmaxf(vmax, __shfl_xor_sync(qmask, vmax, 1));
            vmax = fmaxf(vmax, __shfl_xor_sync(qmask, vmax, 2));
            if (vmax > mr1 - 25.0f) {
                float newm = fmaxf(mr1, vmax);
                float se = 0.0f;
                #pragma unroll
                for (int u = 0; u < 16; u++) se += __expf(sv[u] - newm);
                se += __shfl_xor_sync(qmask, se, 1);
                se += __shfl_xor_sync(qmask, se, 2);
                sr1 = sr1 * __expf(mr1 - newm) + se;
                mr1 = newm;
            }
        }
    }

    if (t == 0) {
        size_t r0 = (size_t)bh * LL + row0;
        size_t r1 = (size_t)bh * LL + row1;
        g_m[r0] = mr0; g_s[r0] = sr0; g_c[r0] = mr0 + __logf(sr0);
        g_m[r1] = mr1; g_s[r1] = sr1; g_c[r1] = mr1 + __logf(sr1);
    }
}

// =====================================================================
// Context: P streamed gmem->reg, V plain smem tile + tile cutoff
// =====================================================================
__global__ __launch_bounds__(256) void context_kernel()
{
    __shared__ unsigned Vs[64][72];   // [d][key] tf32

    const int bh = blockIdx.y, b = bh >> 4, hh = bh & 15;
    const int q0 = blockIdx.x * 128;
    const int tid = threadIdx.x, lane = tid & 31, warp = tid >> 5;
    const int g = lane >> 2, t = lane & 3;

    const int row0 = q0 + warp * 16 + g;
    const int row1 = row0 + 8;
    const int qt = row0 >> 6;
    const float m0 = g_m[(size_t)bh * LL + row0];
    const float m1 = g_m[(size_t)bh * LL + row1];
    const float is0 = 1.0f / g_s[(size_t)bh * LL + row0];
    const float is1 = 1.0f / g_s[(size_t)bh * LL + row1];

    const float* Pr0 = &g_P[((size_t)bh * LL + row0) * LL + 2 * t];
    const float* Pr1 = Pr0 + 8 * LL;

    const int vd = tid & 63, vseg = tid >> 6;

    float c4[8][4] = {};

    for (int kc = 0; kc < LL; kc += 64) {
        __syncthreads();
        {
            const float* vb = &g_V[((size_t)bh * LL + kc + vseg * 16) * DK + vd];
            #pragma unroll
            for (int c = 0; c < 4; c++) {
                unsigned u[4];
                #pragma unroll
                for (int i2 = 0; i2 < 4; i2++)
                    u[i2] = f2tf(vb[(size_t)(c * 4 + i2) * DK]);
                *(uint4*)&Vs[vd][vseg * 16 + 4 * c] = *(uint4*)u;
            }
        }
        __syncthreads();

        if (abs(qt - (kc >> 6)) >= SKIPT) continue;   // dead tile: P never written

        #pragma unroll
        for (int j = 0; j < 8; j++) {
            float2 lo = __ldcs((const float2*)(Pr0 + kc + 8 * j));
            float2 hi = __ldcs((const float2*)(Pr1 + kc + 8 * j));
            unsigned a[4];
            a[0] = f2tf(__expf(lo.x - m0));
            a[1] = f2tf(__expf(hi.x - m1));
            a[2] = f2tf(__expf(lo.y - m0));
            a[3] = f2tf(__expf(hi.y - m1));
            #pragma unroll
            for (int jn = 0; jn < 8; jn++) {
                uint2 bb = *(const uint2*)&Vs[jn * 8 + g][8 * j + 2 * t];
                unsigned bfr[2] = {bb.x, bb.y};
                mma8(c4[jn], a, bfr);
            }
        }
    }

    float* Cr0 = &g_C[((size_t)(b * LL + row0)) * DM + hh * 64 + 2 * t];
    float* Cr1 = &g_C[((size_t)(b * LL + row1)) * DM + hh * 64 + 2 * t];
    #pragma unroll
    for (int jn = 0; jn < 8; jn++) {
        *(float2*)(Cr0 + jn * 8) = make_float2(c4[jn][0] * is0, c4[jn][1] * is0);
        *(float2*)(Cr1 + jn * 8) = make_float2(c4[jn][2] * is1, c4[jn][3] * is1);
    }
}

// =====================================================================
// Head-mean of attention + tile cutoff (write exact 0 for dead tiles)
// =====================================================================
__global__ void mean_kernel(float* __restrict__ outmean)
{
    size_t idx4 = (size_t)blockIdx.x * 256 + threadIdx.x;
    int k4 = (int)(idx4 & (LL / 4 - 1)) * 4;
    size_t bq = idx4 / (LL / 4);
    int q = (int)(bq & (LL - 1));
    int b = (int)(bq >> 11);

    if (abs((q >> 6) - (k4 >> 6)) >= SKIPT) {   // dead tile: prob < e^-74
        *(float4*)&outmean[bq * LL + k4] = make_float4(0.f, 0.f, 0.f, 0.f);
        return;
    }

    float ax = 0, ay = 0, az = 0, aw = 0;
    #pragma unroll
    for (int h = 0; h < NH; h++) {
        int bh = b * NH + h;
        float cc = g_c[(size_t)bh * LL + q];
        float4 v = __ldcs((const float4*)&g_P[((size_t)bh * LL + q) * LL + k4]);
        ax += __expf(v.x - cc); ay += __expf(v.y - cc);
        az += __expf(v.z - cc); aw += __expf(v.w - cc);
    }
    const float inv = 1.0f / NH;
    *(float4*)&outmean[bq * LL + k4] = make_float4(ax*inv, ay*inv, az*inv, aw*inv);
}

// =====================================================================
// Output projection: tf32 MMA, 128m x 64n block  [proven R12]
// =====================================================================
__global__ __launch_bounds__(256) void out_tf32(const float* __restrict__ bo,
                                                float* __restrict__ out)
{
    __shared__ unsigned Ws[64][72];

    const float* WT = g_WT[3];
    const int n0 = blockIdx.x * 64, m0 = blockIdx.y * 128;
    const int tid = threadIdx.x, lane = tid & 31, warp = tid >> 5;
    const int g = lane >> 2, t = lane & 3;

    const int row0 = m0 + warp * 16 + g, row1 = row0 + 8;
    const float* a0p = g_C + (size_t)row0 * DM + 2 * t;
    const float* a1p = g_C + (size_t)row1 * DM + 2 * t;

    const int wn = tid >> 2, wk = (tid & 3) * 16;
    const float* wfill = WT + (size_t)(n0 + wn) * DM + wk;

    float c4[8][4] = {};

    for (int k0 = 0; k0 < DM; k0 += 64) {
        __syncthreads();
        #pragma unroll
        for (int c = 0; c < 4; c++) {
            float4 v = *(const float4*)(wfill + k0 + c * 4);
            unsigned u[4] = {f2tf(v.x), f2tf(v.y), f2tf(v.z), f2tf(v.w)};
            *(uint4*)&Ws[wn][wk + 4 * c] = *(uint4*)u;
        }
        __syncthreads();
        #pragma unroll
        for (int j = 0; j < 8; j++) {
            float2 lo = *(const float2*)(a0p + k0 + 8 * j);
            float2 hi = *(const float2*)(a1p + k0 + 8 * j);
            unsigned a[4] = {f2tf(lo.x), f2tf(hi.x), f2tf(lo.y), f2tf(hi.y)};
            #pragma unroll
            for (int jn = 0; jn < 8; jn++) {
                uint2 bb = *(const uint2*)&Ws[jn * 8 + g][8 * j + 2 * t];
                unsigned bfr[2] = {bb.x, bb.y};
                mma8(c4[jn], a, bfr);
            }
        }
    }

    #pragma unroll
    for (int jn = 0; jn < 8; jn++) {
        int gn = n0 + jn * 8 + 2 * t;
        float bsx = bo[gn], bsy = bo[gn + 1];
        *(float2*)&out[(size_t)row0 * DM + gn] = make_float2(c4[jn][0] + bsx, c4[jn][1] + bsy);
        *(float2*)&out[(size_t)row1 * DM + gn] = make_float2(c4[jn][2] + bsx, c4[jn][3] + bsy);
    }
}

// ---------------- launch ----------------
extern "C" void kernel_launch(void* const* d_in, const int* in_sizes, int n_in,
                              void* d_out, int out_size)
{
    const float* x     = (const float*)d_in[0];
    const float* delta = (const float*)d_in[1];
    const float* Wq    = (const float*)d_in[2];
    const float* bq    = (const float*)d_in[3];
    const float* Wk    = (const float*)d_in[4];
    const float* bk    = (const float*)d_in[5];
    const float* Wv    = (const float*)d_in[6];
    const float* bv    = (const float*)d_in[7];
    const float* Wo    = (const float*)d_in[8];
    const float* bo    = (const float*)d_in[9];
    float* out = (float*)d_out;
    float* outmean = out + (size_t)BB * LL * DM;

    rb_kernel<<<(BB * LL + 255) / 256, 256>>>(delta);
    wt_kernel<<<dim3(32, 32, 4), dim3(32, 8)>>>(Wq, Wk, Wv, Wo);
    qkv_tf32<<<dim3(DM / 64, (BB * LL) / 128, 3), 256>>>(x, delta, bq, bk, bv);
    scores_kernel<<<dim3(LL / 128, BH), 256>>>();
    context_kernel<<<dim3(LL / 128, BH), 256>>>();
    mean_kernel<<<(unsigned)((size_t)BB * LL * LL / 4 / 256), 256>>>(outmean);
    out_tf32<<<dim3(DM / 64, (BB * LL) / 128), 256>>>(bo, out);
}